// round 16
// baseline (speedup 1.0000x reference)
#include <cuda_runtime.h>
#include <cstdint>

// RandomTimeMask: out[n,c,l] = x[n,c,l] if ((l - starts[n,c]) mod L) >= L/4 else 0
// x [128,12,32768] fp32, starts [128,12] int32. L=32768, mask_len=8192.
//
// R16 = R11/R12 structure in 256-bit (v8) accesses. sm_103a ld/st.global.v8
// halves LDG/STG instruction count and L1tex wavefronts (warp access = 1024B
// = 8 full lines). Streams stay 128B-aligned; uniform 1-zero+3-copy pairing
// per thread (load/store pacing); .cs hints; clamped overlap (idempotent).
// Traffic stays at the 336 MB minimum (144R + 192W).

static constexpr int L    = 32768;
static constexpr int ML   = 8192;          // mask_len
static constexpr int LM1  = L - 1;
static constexpr int VPR  = L / 4;         // 8192 float4 per row (edge path)
static constexpr int VM1  = VPR - 1;
static constexpr int V8PR = L / 8;         // 4096 float8 per row
static constexpr int V8M1 = V8PR - 1;      // 4095
static constexpr int THREADS = 256;
static constexpr int SPLITS  = 4;
static constexpr int JTOT    = 1008;       // 63 segments * 16 float8
static constexpr int JSPAN   = 252;        // JTOT / SPLITS (multiple of 4 -> 128B align)

struct f8 { float4 a, b; };

__device__ __forceinline__ f8 ldcs_v8(const float* p) {
    f8 v;
    asm volatile("ld.global.cs.v8.b32 {%0,%1,%2,%3,%4,%5,%6,%7}, [%8];"
        : "=f"(v.a.x), "=f"(v.a.y), "=f"(v.a.z), "=f"(v.a.w),
          "=f"(v.b.x), "=f"(v.b.y), "=f"(v.b.z), "=f"(v.b.w)
        : "l"(p));
    return v;
}

__device__ __forceinline__ void stcs_v8(float* p, const f8& v) {
    asm volatile("st.global.cs.v8.b32 [%0], {%1,%2,%3,%4,%5,%6,%7,%8};"
        :: "l"(p),
           "f"(v.a.x), "f"(v.a.y), "f"(v.a.z), "f"(v.a.w),
           "f"(v.b.x), "f"(v.b.y), "f"(v.b.z), "f"(v.b.w)
        : "memory");
}

__global__ __launch_bounds__(THREADS)
void random_time_mask_kernel(const float* __restrict__ x,
                             const int* __restrict__ starts,
                             float* __restrict__ out)
{
    const int row   = blockIdx.x >> 2;            // 0..1535
    const int split = blockIdx.x & 3;             // 0..3
    const int s     = __ldg(&starts[row]);        // 0 <= s < L

    const float* __restrict__ xr = x   + (size_t)row * L;
    float*       __restrict__ yr = out + (size_t)row * L;

    const int sa  = s >> 7;                       // segment (128 elems) w/ mask start
    const int za8 = (sa + 1)  << 4;               // zero-stream base (float8 units)
    const int ca8 = (sa + 65) << 4;               // copy-stream base (float8 units)

    // Exactly one paired iteration per thread; clamp makes coverage exact
    // ([0,1011] -> [0,1007]) with idempotent duplicate writes.
    const int j = min(split * JSPAN + (int)threadIdx.x, JTOT - 1);

    const int mz = (za8 + j)        & V8M1;
    const int c0 = (ca8 + j)        & V8M1;
    const int c1 = (ca8 + 1008 + j) & V8M1;
    const int c2 = (ca8 + 2016 + j) & V8M1;

    const f8 v0 = ldcs_v8(xr + (c0 << 3));
    const f8 v1 = ldcs_v8(xr + (c1 << 3));
    const f8 v2 = ldcs_v8(xr + (c2 << 3));

    f8 z;
    z.a = make_float4(0.f, 0.f, 0.f, 0.f);
    z.b = z.a;
    stcs_v8(yr + (mz << 3), z);
    stcs_v8(yr + (c0 << 3), v0);
    stcs_v8(yr + (c1 << 3), v1);
    stcs_v8(yr + (c2 << 3), v2);

    // Leftover segments (4 per row): sa and sa+64 (partially masked),
    // sa+254 and sa+255 (fully kept). Per-lane float4 select path, 1 warp each.
    if (split == 0 && threadIdx.x < 128) {
        const float4* __restrict__ xr4 = (const float4*)xr;
        float4*       __restrict__ yr4 = (float4*)yr;
        const int w    = threadIdx.x >> 5;        // 0..3
        const int lane = threadIdx.x & 31;
        const int seg  = (w == 0) ? sa
                       : (w == 1) ? sa + 64
                       : (w == 2) ? sa + 254
                                  : sa + 255;
        const int v = ((seg << 5) + lane) & VM1;
        float4 t = xr4[v];
        const int base = v << 2;
        const int o0 = (base     - s) & LM1;
        const int o1 = (base + 1 - s) & LM1;
        const int o2 = (base + 2 - s) & LM1;
        const int o3 = (base + 3 - s) & LM1;
        t.x = (o0 < ML) ? 0.0f : t.x;
        t.y = (o1 < ML) ? 0.0f : t.y;
        t.z = (o2 < ML) ? 0.0f : t.z;
        t.w = (o3 < ML) ? 0.0f : t.w;
        yr4[v] = t;
    }
}

extern "C" void kernel_launch(void* const* d_in, const int* in_sizes, int n_in,
                              void* d_out, int out_size)
{
    const float* x      = (const float*)d_in[0];
    const int*   starts = (const int*)d_in[1];
    float*       out    = (float*)d_out;

    const int n_rows = in_sizes[1];                // 128*12 = 1536
    random_time_mask_kernel<<<n_rows * SPLITS, THREADS>>>(x, starts, out);
}

// round 17
// speedup vs baseline: 1.0022x; 1.0022x over previous
#include <cuda_runtime.h>
#include <cstdint>

// RandomTimeMask: out[n,c,l] = x[n,c,l] if ((l - starts[n,c]) mod L) >= L/4 else 0
// x [128,12,32768] fp32, starts [128,12] int32. L=32768, mask_len=8192.
//
// R17 = R16 (256-bit v8 accesses, fastest measured kernel) + balanced edge
// handling: each of the 4 splits handles exactly ONE leftover segment with
// one warp, so all blocks are homogeneous (R16 put all 4 edge segments on
// split 0 -> longest-pole blocks set the tail).
// Streams 128B-aligned, 1-zero+3-copy pacing, .cs hints, idempotent clamp.
// Traffic at the 336 MB minimum (144R + 192W).

static constexpr int L    = 32768;
static constexpr int ML   = 8192;          // mask_len
static constexpr int LM1  = L - 1;
static constexpr int VPR  = L / 4;         // 8192 float4 per row (edge path)
static constexpr int VM1  = VPR - 1;
static constexpr int V8PR = L / 8;         // 4096 float8 per row
static constexpr int V8M1 = V8PR - 1;      // 4095
static constexpr int THREADS = 256;
static constexpr int SPLITS  = 4;
static constexpr int JTOT    = 1008;       // 63 segments * 16 float8
static constexpr int JSPAN   = 252;        // JTOT / SPLITS (multiple of 4 -> 128B align)

struct f8 { float4 a, b; };

__device__ __forceinline__ f8 ldcs_v8(const float* p) {
    f8 v;
    asm volatile("ld.global.cs.v8.b32 {%0,%1,%2,%3,%4,%5,%6,%7}, [%8];"
        : "=f"(v.a.x), "=f"(v.a.y), "=f"(v.a.z), "=f"(v.a.w),
          "=f"(v.b.x), "=f"(v.b.y), "=f"(v.b.z), "=f"(v.b.w)
        : "l"(p));
    return v;
}

__device__ __forceinline__ void stcs_v8(float* p, const f8& v) {
    asm volatile("st.global.cs.v8.b32 [%0], {%1,%2,%3,%4,%5,%6,%7,%8};"
        :: "l"(p),
           "f"(v.a.x), "f"(v.a.y), "f"(v.a.z), "f"(v.a.w),
           "f"(v.b.x), "f"(v.b.y), "f"(v.b.z), "f"(v.b.w)
        : "memory");
}

__global__ __launch_bounds__(THREADS)
void random_time_mask_kernel(const float* __restrict__ x,
                             const int* __restrict__ starts,
                             float* __restrict__ out)
{
    const int row   = blockIdx.x >> 2;            // 0..1535
    const int split = blockIdx.x & 3;             // 0..3
    const int s     = __ldg(&starts[row]);        // 0 <= s < L

    const float* __restrict__ xr = x   + (size_t)row * L;
    float*       __restrict__ yr = out + (size_t)row * L;

    const int sa  = s >> 7;                       // segment (128 elems) w/ mask start
    const int za8 = (sa + 1)  << 4;               // zero-stream base (float8 units)
    const int ca8 = (sa + 65) << 4;               // copy-stream base (float8 units)

    // Exactly one paired iteration per thread; clamp makes coverage exact
    // with idempotent duplicate writes.
    const int j = min(split * JSPAN + (int)threadIdx.x, JTOT - 1);

    const int mz = (za8 + j)        & V8M1;
    const int c0 = (ca8 + j)        & V8M1;
    const int c1 = (ca8 + 1008 + j) & V8M1;
    const int c2 = (ca8 + 2016 + j) & V8M1;

    const f8 v0 = ldcs_v8(xr + (c0 << 3));
    const f8 v1 = ldcs_v8(xr + (c1 << 3));
    const f8 v2 = ldcs_v8(xr + (c2 << 3));

    f8 z;
    z.a = make_float4(0.f, 0.f, 0.f, 0.f);
    z.b = z.a;
    stcs_v8(yr + (mz << 3), z);
    stcs_v8(yr + (c0 << 3), v0);
    stcs_v8(yr + (c1 << 3), v1);
    stcs_v8(yr + (c2 << 3), v2);

    // Leftover segments (4 per row): sa and sa+64 (partially masked),
    // sa+254 and sa+255 (fully kept). One warp in EACH split handles one
    // segment -> homogeneous blocks. Per-lane float4 select path.
    if (threadIdx.x < 32) {
        const float4* __restrict__ xr4 = (const float4*)xr;
        float4*       __restrict__ yr4 = (float4*)yr;
        const int lane = threadIdx.x;
        const int seg  = (split == 0) ? sa
                       : (split == 1) ? sa + 64
                       : (split == 2) ? sa + 254
                                      : sa + 255;
        const int v = ((seg << 5) + lane) & VM1;
        float4 t = xr4[v];
        const int base = v << 2;
        const int o0 = (base     - s) & LM1;
        const int o1 = (base + 1 - s) & LM1;
        const int o2 = (base + 2 - s) & LM1;
        const int o3 = (base + 3 - s) & LM1;
        t.x = (o0 < ML) ? 0.0f : t.x;
        t.y = (o1 < ML) ? 0.0f : t.y;
        t.z = (o2 < ML) ? 0.0f : t.z;
        t.w = (o3 < ML) ? 0.0f : t.w;
        yr4[v] = t;
    }
}

extern "C" void kernel_launch(void* const* d_in, const int* in_sizes, int n_in,
                              void* d_out, int out_size)
{
    const float* x      = (const float*)d_in[0];
    const int*   starts = (const int*)d_in[1];
    float*       out    = (float*)d_out;

    const int n_rows = in_sizes[1];                // 128*12 = 1536
    random_time_mask_kernel<<<n_rows * SPLITS, THREADS>>>(x, starts, out);
}